// round 13
// baseline (speedup 1.0000x reference)
#include <cuda_runtime.h>

// PaillerMLP: out = W3 @ ((W2 @ ((W1 @ x + b1)^2) + b2)^2) + b3
// D_IN=4096, D_HID=8192, D_OUT=1000, fp32. HBM-bound: ~415 MiB weights.
//
// R5  (3 kernels, warp-per-row, grid 1024): 78.3us, DRAM 71%.
//     1024 blocks / ~600 resident slots = 1.73 waves -> ~86% util ceiling.
// R7/R10 (persistent variants): 78-84us — sync machinery ate the tail gains.
// R12: back to 3 plain kernels, but layers 1-2 use EXACTLY 2 rows per warp
//      (grid 512 = one wave, perfect balance, no tails). The row pair shares
//      x reads from smem; 8 LDG.128 in flight per warp (4 per row).

#define D_IN  4096
#define D_HID 8192
#define D_OUT 1000

// Intermediate activations (scratch via __device__ globals — no allocs).
__device__ float g_h1[D_HID];
__device__ float g_h2[D_HID];

// ---------------------------------------------------------------------------
// Layers 1-2: two rows per warp, 8 warps/block -> 16 rows/block.
// grid = M/16 (512 for M=8192) -> single co-resident wave (capacity ~600).
// ---------------------------------------------------------------------------
template <int K, bool SQUARE>
__global__ __launch_bounds__(256, 4)
void matvec2_kernel(const float* __restrict__ W,
                    const float* __restrict__ x,
                    const float* __restrict__ b,
                    float* __restrict__ out)
{
    __shared__ float sx[K];               // 16KB (K=4096) or 32KB (K=8192)

    const int tid = threadIdx.x;

    // Stage x once per block (shared by 16 rows).
    const float4* x4  = reinterpret_cast<const float4*>(x);
    float4*       sx4s = reinterpret_cast<float4*>(sx);
    #pragma unroll
    for (int i = tid; i < K / 4; i += 256)
        sx4s[i] = __ldg(&x4[i]);
    __syncthreads();

    const int wid  = tid >> 5;
    const int lane = tid & 31;
    const int gw   = blockIdx.x * 8 + wid;   // global warp id
    const int r0   = gw * 2;
    const int r1   = gw * 2 + 1;

    const float4* W0 = reinterpret_cast<const float4*>(W) + (size_t)r0 * (K / 4);
    const float4* W1 = reinterpret_cast<const float4*>(W) + (size_t)r1 * (K / 4);
    const float4* sx4 = reinterpret_cast<const float4*>(sx);

    constexpr int ITERS = K / 4 / 32;     // float4 per lane per row (32 or 64)

    float a0e = 0.f, a0o = 0.f;           // row0 accumulators (even/odd)
    float a1e = 0.f, a1o = 0.f;           // row1 accumulators

    // 8 streaming LDG.128 in flight per warp (4 per row), x read once per
    // position and consumed by both rows' FMAs.
    #pragma unroll 1
    for (int base = 0; base < ITERS; base += 4) {
        float4 w0[4], w1[4];
        #pragma unroll
        for (int u = 0; u < 4; u++) w0[u] = __ldcs(&W0[(base + u) * 32 + lane]);
        #pragma unroll
        for (int u = 0; u < 4; u++) w1[u] = __ldcs(&W1[(base + u) * 32 + lane]);

        #pragma unroll
        for (int u = 0; u < 4; u++) {
            const float4 xv = sx4[(base + u) * 32 + lane];
            if (u & 1) {
                a0o += w0[u].x*xv.x + w0[u].y*xv.y + w0[u].z*xv.z + w0[u].w*xv.w;
                a1o += w1[u].x*xv.x + w1[u].y*xv.y + w1[u].z*xv.z + w1[u].w*xv.w;
            } else {
                a0e += w0[u].x*xv.x + w0[u].y*xv.y + w0[u].z*xv.z + w0[u].w*xv.w;
                a1e += w1[u].x*xv.x + w1[u].y*xv.y + w1[u].z*xv.z + w1[u].w*xv.w;
            }
        }
    }

    float acc0 = a0e + a0o;
    float acc1 = a1e + a1o;

    // Two independent warp reductions, interleaved.
    #pragma unroll
    for (int off = 16; off; off >>= 1) {
        acc0 += __shfl_xor_sync(0xffffffffu, acc0, off);
        acc1 += __shfl_xor_sync(0xffffffffu, acc1, off);
    }

    if (lane == 0) {
        float v0 = acc0 + __ldg(&b[r0]);
        float v1 = acc1 + __ldg(&b[r1]);
        if (SQUARE) { v0 = v0 * v0; v1 = v1 * v1; }
        out[r0] = v0;
        out[r1] = v1;
    }
}

// ---------------------------------------------------------------------------
// Layer 3: classic warp-per-row (1000 rows -> 125 blocks), batch-8 loads.
// ---------------------------------------------------------------------------
template <int K>
__global__ __launch_bounds__(256, 4)
void matvec1_kernel(const float* __restrict__ W,
                    const float* __restrict__ x,
                    const float* __restrict__ b,
                    float* __restrict__ out,
                    int M)
{
    __shared__ float sx[K];

    const int tid = threadIdx.x;
    const float4* x4  = reinterpret_cast<const float4*>(x);
    float4*       sx4s = reinterpret_cast<float4*>(sx);
    #pragma unroll
    for (int i = tid; i < K / 4; i += 256)
        sx4s[i] = __ldg(&x4[i]);
    __syncthreads();

    const int wid  = tid >> 5;
    const int lane = tid & 31;
    const int row  = blockIdx.x * 8 + wid;
    if (row >= M) return;

    const float4* Wp  = reinterpret_cast<const float4*>(W) + (size_t)row * (K / 4);
    const float4* sx4 = reinterpret_cast<const float4*>(sx);

    constexpr int ITERS = K / 4 / 32;     // 64

    float ae = 0.f, ao = 0.f;
    #pragma unroll 1
    for (int base = 0; base < ITERS; base += 8) {
        float4 w[8];
        #pragma unroll
        for (int u = 0; u < 8; u++) w[u] = __ldcs(&Wp[(base + u) * 32 + lane]);
        #pragma unroll
        for (int u = 0; u < 8; u++) {
            const float4 xv = sx4[(base + u) * 32 + lane];
            if (u & 1) ao += w[u].x*xv.x + w[u].y*xv.y + w[u].z*xv.z + w[u].w*xv.w;
            else       ae += w[u].x*xv.x + w[u].y*xv.y + w[u].z*xv.z + w[u].w*xv.w;
        }
    }

    float acc = ae + ao;
    #pragma unroll
    for (int off = 16; off; off >>= 1)
        acc += __shfl_xor_sync(0xffffffffu, acc, off);

    if (lane == 0)
        out[row] = acc + __ldg(&b[row]);
}

extern "C" void kernel_launch(void* const* d_in, const int* in_sizes, int n_in,
                              void* d_out, int out_size)
{
    const float* x  = (const float*)d_in[0];
    const float* W1 = (const float*)d_in[1];
    const float* b1 = (const float*)d_in[2];
    const float* W2 = (const float*)d_in[3];
    const float* b2 = (const float*)d_in[4];
    const float* W3 = (const float*)d_in[5];
    const float* b3 = (const float*)d_in[6];
    float* out = (float*)d_out;

    float *h1, *h2;
    cudaGetSymbolAddress((void**)&h1, g_h1);
    cudaGetSymbolAddress((void**)&h2, g_h2);

    // Layer 1: [8192 x 4096], 16 rows/block -> 512 blocks (single wave).
    matvec2_kernel<D_IN, true><<<D_HID / 16, 256>>>(W1, x, b1, h1);

    // Layer 2: [8192 x 8192], 16 rows/block -> 512 blocks (single wave).
    matvec2_kernel<D_HID, true><<<D_HID / 16, 256>>>(W2, h1, b2, h2);

    // Layer 3: [1000 x 8192], warp-per-row -> 125 blocks.
    matvec1_kernel<D_HID><<<D_OUT / 8, 256>>>(W3, h2, b3, out, D_OUT);
}

// round 14
// speedup vs baseline: 1.0926x; 1.0926x over previous
#include <cuda_runtime.h>

// PaillerMLP: out = W3 @ ((W2 @ ((W1 @ x + b1)^2) + b2)^2) + b3
// D_IN=4096, D_HID=8192, D_OUT=1000, fp32. HBM-bound: ~415 MiB weights.
//
// History: every uniform-item schedule pinned at ~86% utilization
// (items/worker = 1.73 -> makespan ceil = 2). R12 proved it's placement
// quantization, not warps. Fix: items/worker ~ 7.
// R13: layers 1-2 use item = 2 rows with 4 warps per row (K split across
//      warps, intra-block smem reduction). 4096 items over ~592 blocks
//      -> 6.9 items/block -> ~99% static balance. No finalize kernels,
//      no atomics, no persistence. Layer 3 stays warp-per-row.

#define D_IN  4096
#define D_HID 8192
#define D_OUT 1000

__device__ float g_h1[D_HID];
__device__ float g_h2[D_HID];

__device__ __forceinline__ void split(int total, int g, int b, int& s, int& e)
{
    int base = total / g, rem = total % g;
    s = b * base + (b < rem ? b : rem);
    e = s + base + (b < rem ? 1 : 0);
}

// ---------------------------------------------------------------------------
// Layers 1-2: cooperative matvec.
// Block = 8 warps. Item = 2 consecutive rows; warps 0-3 -> row 2i (K-chunks
// 0-3), warps 4-7 -> row 2i+1. Each warp streams a contiguous K/4 chunk
// (8 or 16 LDG.128 per lane, front-batched 8 at a time). Warp partials go to
// double-buffered smem slots; one __syncthreads per item; tid 0 / tid 32
// combine 4 partials + bias, square, store.
// ---------------------------------------------------------------------------
template <int K, bool SQUARE>
__global__ __launch_bounds__(256, 4)
void matvec_coop(const float* __restrict__ W,
                 const float* __restrict__ x,
                 const float* __restrict__ b,
                 float* __restrict__ out,
                 int M)
{
    __shared__ float sx[K];                 // 16KB (K=4096) / 32KB (K=8192)
    __shared__ float spart[2][8];

    const int tid = threadIdx.x;

    // Stage x once per block; reused by ~7 items (14 rows).
    {
        const float4* x4 = reinterpret_cast<const float4*>(x);
        float4* s4 = reinterpret_cast<float4*>(sx);
        #pragma unroll
        for (int i = tid; i < K / 4; i += 256)
            s4[i] = __ldg(&x4[i]);
    }
    __syncthreads();

    const int wid  = tid >> 5;
    const int lane = tid & 31;
    const int sub  = wid & 3;               // K-chunk index within the row
    const int half = wid >> 2;              // which row of the pair

    constexpr int C4 = K / 16;              // float4 per K-chunk (256 or 512)
    constexpr int PL = C4 / 32;             // float4 per lane (8 or 16)

    const float4* sxc = reinterpret_cast<const float4*>(sx) + sub * C4;

    int s, e;
    split(M / 2, gridDim.x, blockIdx.x, s, e);

    int buf = 0;
    for (int it = s; it < e; ++it, buf ^= 1) {
        const int row = it * 2 + half;
        const float4* Wp = reinterpret_cast<const float4*>(W)
                         + (size_t)row * (K / 4) + sub * C4;

        float ae = 0.f, ao = 0.f;
        #pragma unroll
        for (int base = 0; base < PL; base += 8) {
            float4 w[8];
            #pragma unroll
            for (int u = 0; u < 8; u++)
                w[u] = __ldcs(&Wp[(base + u) * 32 + lane]);   // streamed once
            #pragma unroll
            for (int u = 0; u < 8; u++) {
                const float4 xv = sxc[(base + u) * 32 + lane];
                if (u & 1) ao += w[u].x*xv.x + w[u].y*xv.y + w[u].z*xv.z + w[u].w*xv.w;
                else       ae += w[u].x*xv.x + w[u].y*xv.y + w[u].z*xv.z + w[u].w*xv.w;
            }
        }

        float acc = ae + ao;
        #pragma unroll
        for (int off = 16; off; off >>= 1)
            acc += __shfl_xor_sync(0xffffffffu, acc, off);

        if (lane == 0)
            spart[buf][wid] = acc;
        __syncthreads();

        // Leaders of warps 0 and 1 finish the two rows. Readers of spart[buf]
        // run concurrently with the next item's writes to spart[buf^1]; the
        // next __syncthreads orders everything before spart[buf] is reused.
        if (tid == 0 || tid == 32) {
            const int h = tid >> 5;
            const int r = it * 2 + h;
            float v = ((spart[buf][h*4+0] + spart[buf][h*4+1])
                     + (spart[buf][h*4+2] + spart[buf][h*4+3]))
                     + __ldg(&b[r]);
            if (SQUARE) v = v * v;
            out[r] = v;
        }
    }
}

// ---------------------------------------------------------------------------
// Layer 3: warp-per-row (1000 rows -> 125 blocks), batch-8 streaming loads.
// ---------------------------------------------------------------------------
template <int K>
__global__ __launch_bounds__(256, 4)
void matvec1_kernel(const float* __restrict__ W,
                    const float* __restrict__ x,
                    const float* __restrict__ b,
                    float* __restrict__ out,
                    int M)
{
    __shared__ float sx[K];

    const int tid = threadIdx.x;
    {
        const float4* x4 = reinterpret_cast<const float4*>(x);
        float4* s4 = reinterpret_cast<float4*>(sx);
        #pragma unroll
        for (int i = tid; i < K / 4; i += 256)
            s4[i] = __ldg(&x4[i]);
    }
    __syncthreads();

    const int wid  = tid >> 5;
    const int lane = tid & 31;
    const int row  = blockIdx.x * 8 + wid;
    if (row >= M) return;

    const float4* Wp  = reinterpret_cast<const float4*>(W) + (size_t)row * (K / 4);
    const float4* sx4 = reinterpret_cast<const float4*>(sx);

    constexpr int ITERS = K / 4 / 32;

    float ae = 0.f, ao = 0.f;
    #pragma unroll 1
    for (int base = 0; base < ITERS; base += 8) {
        float4 w[8];
        #pragma unroll
        for (int u = 0; u < 8; u++)
            w[u] = __ldcs(&Wp[(base + u) * 32 + lane]);
        #pragma unroll
        for (int u = 0; u < 8; u++) {
            const float4 xv = sx4[(base + u) * 32 + lane];
            if (u & 1) ao += w[u].x*xv.x + w[u].y*xv.y + w[u].z*xv.z + w[u].w*xv.w;
            else       ae += w[u].x*xv.x + w[u].y*xv.y + w[u].z*xv.z + w[u].w*xv.w;
        }
    }

    float acc = ae + ao;
    #pragma unroll
    for (int off = 16; off; off >>= 1)
        acc += __shfl_xor_sync(0xffffffffu, acc, off);

    if (lane == 0)
        out[row] = acc + __ldg(&b[row]);
}

extern "C" void kernel_launch(void* const* d_in, const int* in_sizes, int n_in,
                              void* d_out, int out_size)
{
    const float* x  = (const float*)d_in[0];
    const float* W1 = (const float*)d_in[1];
    const float* b1 = (const float*)d_in[2];
    const float* W2 = (const float*)d_in[3];
    const float* b2 = (const float*)d_in[4];
    const float* W3 = (const float*)d_in[5];
    const float* b3 = (const float*)d_in[6];
    float* out = (float*)d_out;

    float *h1, *h2;
    cudaGetSymbolAddress((void**)&h1, g_h1);
    cudaGetSymbolAddress((void**)&h2, g_h2);

    // Grid = resident capacity (host queries are legal under graph capture;
    // value freezes into the graph). items/block ~ 6.9 -> ~99% balance.
    int dev = 0;
    cudaGetDevice(&dev);
    int sms = 148;
    cudaDeviceGetAttribute(&sms, cudaDevAttrMultiProcessorCount, dev);

    int nb1 = 0, nb2 = 0;
    cudaOccupancyMaxActiveBlocksPerMultiprocessor(&nb1, matvec_coop<D_IN,  true>, 256, 0);
    cudaOccupancyMaxActiveBlocksPerMultiprocessor(&nb2, matvec_coop<D_HID, true>, 256, 0);
    if (nb1 < 1) nb1 = 1;
    if (nb2 < 1) nb2 = 1;
    int g1 = sms * nb1;
    int g2 = sms * nb2;
    if (g1 > D_HID / 2) g1 = D_HID / 2;
    if (g2 > D_HID / 2) g2 = D_HID / 2;

    // Layer 1: [8192 x 4096]
    matvec_coop<D_IN, true><<<g1, 256>>>(W1, x, b1, h1, D_HID);

    // Layer 2: [8192 x 8192]
    matvec_coop<D_HID, true><<<g2, 256>>>(W2, h1, b2, h2, D_HID);

    // Layer 3: [1000 x 8192]
    matvec1_kernel<D_HID><<<D_OUT / 8, 256>>>(W3, h2, b3, out, D_OUT);
}